// round 14
// baseline (speedup 1.0000x reference)
#include <cuda_runtime.h>
#include <cuda_fp16.h>
#include <cstdint>
#include <cstddef>

// ---------------- problem constants ----------------
#define NCAV     2
#define WIN      8
#define BWIN     2048
#define NTOK     64
#define CH       256
#define NHEAD    8
#define HD       32
#define MROWS    (BWIN*NTOK)    // 131072
#define SCALE_Q  0.17677669529663687f
#define PI_F     3.14159274101257324f

// ---------------- scratch (fp16 pipeline) ----------------
__device__ __half g_xh  [(size_t)MROWS*CH];       // x, fp16
__device__ __half g_qh  [BWIN*NHEAD*NTOK*HD];
__device__ __half g_kh  [BWIN*NHEAD*NTOK*HD];
__device__ __half g_vh  [BWIN*NHEAD*NTOK*HD];
__device__ __half g_aoh [(size_t)MROWS*CH];       // attn output, fp16
__device__ __half g_wqkvh[768*CH];                // [n][k] transposed fp16
__device__ __half g_wph [CH*CH];                  // [n][k] transposed fp16
__device__ float  g_bqkv[768];
__device__ int    g_egoidx[BWIN];

// ---------------- helpers ----------------
__device__ __forceinline__ void mma_f16(float c[4], const uint32_t a[4], const uint32_t b[2]) {
    asm volatile(
        "mma.sync.aligned.m16n8k16.row.col.f32.f16.f16.f32 "
        "{%0,%1,%2,%3},{%4,%5,%6,%7},{%8,%9},{%0,%1,%2,%3};\n"
        : "+f"(c[0]), "+f"(c[1]), "+f"(c[2]), "+f"(c[3])
        : "r"(a[0]), "r"(a[1]), "r"(a[2]), "r"(a[3]), "r"(b[0]), "r"(b[1]));
}

__device__ __forceinline__ void ldsm4(uint32_t& r0, uint32_t& r1, uint32_t& r2, uint32_t& r3,
                                      uint32_t saddr) {
    asm volatile("ldmatrix.sync.aligned.m8n8.x4.shared.b16 {%0,%1,%2,%3}, [%4];\n"
                 : "=r"(r0), "=r"(r1), "=r"(r2), "=r"(r3) : "r"(saddr));
}

__device__ __forceinline__ void ldsm4t(uint32_t& r0, uint32_t& r1, uint32_t& r2, uint32_t& r3,
                                       uint32_t saddr) {
    asm volatile("ldmatrix.sync.aligned.m8n8.x4.trans.shared.b16 {%0,%1,%2,%3}, [%4];\n"
                 : "=r"(r0), "=r"(r1), "=r"(r2), "=r"(r3) : "r"(saddr));
}

__device__ __forceinline__ void cpasync16(void* s, const void* g) {
    uint32_t sa = (uint32_t)__cvta_generic_to_shared(s);
    asm volatile("cp.async.cg.shared.global [%0], [%1], 16;\n" :: "r"(sa), "l"(g));
}

// ---------------- kernel 1: pack weights transposed [n][k] fp16 ----------------
__global__ void pack_kernel(const float* __restrict__ Wq, const float* __restrict__ bq,
                            const float* __restrict__ Wkv, const float* __restrict__ bkv,
                            const float* __restrict__ Wp) {
    int t = blockIdx.x * blockDim.x + threadIdx.x;  // 196608
    int n = t >> 8, k = t & 255;
    g_wqkvh[t] = __float2half_rn((n < CH) ? Wq[k*CH + n] : Wkv[k*512 + (n - CH)]);
    if (t < 768) g_bqkv[t] = (t < CH) ? bq[t] : bkv[t - CH];
    if (t < CH*CH) g_wph[t] = __float2half_rn(Wp[k*CH + n]);
}

// ---------------- kernel 2: x -> fp16 ----------------
__global__ void prep_x(const float* __restrict__ x) {
    size_t i = ((size_t)blockIdx.x * 256 + threadIdx.x) * 8;
    float4 a = *(const float4*)(x + i);
    float4 b = *(const float4*)(x + i + 4);
    __half2 h[4];
    h[0] = __floats2half2_rn(a.x, a.y);
    h[1] = __floats2half2_rn(a.z, a.w);
    h[2] = __floats2half2_rn(b.x, b.y);
    h[3] = __floats2half2_rn(b.z, b.w);
    *(uint4*)(g_xh + i) = *(uint4*)h;
}

// ---------------- kernel 3: ego bias bin index ----------------
__global__ void ego_kernel(const float* __restrict__ A) {
    __shared__ float rx[BWIN], ry[BWIN];
    __shared__ float red[256];
    int tid = threadIdx.x;
    float ex[NCAV], ey[NCAV];
#pragma unroll
    for (int c = 0; c < NCAV; c++) {
        ex[c] = A[c*6 + 0] * 128.0f + A[c*6 + 1] * 128.0f + A[c*6 + 2];
        ey[c] = A[c*6 + 3] * 128.0f + A[c*6 + 4] * 128.0f + A[c*6 + 5];
    }
    float lmax = 0.0f;
    for (int i = tid; i < BWIN; i += 256) {
        int cav = i >> 10, wi = i & 1023;
        int gy = wi >> 5, gx = wi & 31;
        float cx = gx * (float)WIN + WIN * 0.5f;
        float cy = gy * (float)WIN + WIN * 0.5f;
        float rxx = cx - ex[cav], ryy = cy - ey[cav];
        rx[i] = rxx; ry[i] = ryy;
        lmax = fmaxf(lmax, sqrtf(rxx*rxx + ryy*ryy));
    }
    red[tid] = lmax;
    __syncthreads();
    for (int s = 128; s > 0; s >>= 1) {
        if (tid < s) red[tid] = fmaxf(red[tid], red[tid + s]);
        __syncthreads();
    }
    float maxd = red[0] + 1e-6f;
    for (int i = tid; i < BWIN; i += 256) {
        float rxx = rx[i], ryy = ry[i];
        float d = sqrtf(rxx*rxx + ryy*ryy);
        int db = (int)(d / maxd * 3.0f);
        float ang = atan2f(ryy, rxx);
        int ab = (int)((ang + PI_F) / (2.0f * PI_F) * 3.0f);
        g_egoidx[i] = db * 4 + ab;
    }
}

// ---------------- GEMM fp16 (R10 config): resident B + 3-stage streamed A ----
#define BS_OFF(r, c)      ((r)*264 + (c))
#define AS_OFF(st, r, c)  (33792 + ((st)*128 + (r))*40 + (c))

#define ISSUE_A(st, kt) do {                                                  \
    _Pragma("unroll")                                                         \
    for (int ii = 0; ii < 2; ii++) {                                          \
        int c = tid + ii * 256;                                               \
        int row = c >> 2, kc = (c & 3) * 8;                                   \
        cpasync16(&hsm[AS_OFF(st, row, kc)],                                  \
                  Ap + (size_t)(bm0 + row) * 256 + (kt) * 32 + kc);           \
    }                                                                         \
    asm volatile("cp.async.commit_group;\n");                                 \
} while (0)

#define LOAD_FRAGS(buf, st, kglob, ks) do {                                   \
    _Pragma("unroll")                                                         \
    for (int mt = 0; mt < 4; mt++)                                            \
        ldsm4(af[buf][mt][0], af[buf][mt][1], af[buf][mt][2], af[buf][mt][3], \
              smemBase + AS_OFF(st, wm + mt*16 + aRow, (ks) + aCol) * 2);     \
    _Pragma("unroll")                                                         \
    for (int p = 0; p < 2; p++)                                               \
        ldsm4(bf[buf][2*p][0], bf[buf][2*p][1], bf[buf][2*p+1][0], bf[buf][2*p+1][1], \
              smemBase + BS_OFF(wn + p*16 + bRow, (kglob) + (ks) + bCol) * 2);\
} while (0)

__global__ __launch_bounds__(256, 2) void gemm_f16(
    const float* __restrict__ bias_ext, int mode, float* __restrict__ out)
{
    extern __shared__ __half hsm[];
    const __half* __restrict__ Ap    = (mode == 0) ? g_xh : g_aoh;
    const __half* __restrict__ Bp    = (mode == 0) ? g_wqkvh : g_wph;
    const float*  __restrict__ biasp = (mode == 0) ? g_bqkv : bias_ext;

    const int bm0 = blockIdx.y * 128;
    const int bn0 = blockIdx.x * 128;
    int tid = threadIdx.x, warp = tid >> 5, lane = tid & 31;
    int wm = (warp & 1) * 64, wn = (warp >> 1) * 32;
    int gid = lane >> 2, tig = lane & 3;

    uint32_t smemBase = (uint32_t)__cvta_generic_to_shared(hsm);
    int aRow = lane & 15;
    int aCol = (lane >> 4) * 8;
    int bRow = ((lane >> 4) << 3) + (lane & 7);
    int bCol = ((lane >> 3) & 1) * 8;

    // prologue: resident B tile (group 0), then A stages 0 and 1
#pragma unroll
    for (int ii = 0; ii < 16; ii++) {
        int c = tid + ii * 256;
        int row = c >> 5, kc = (c & 31) * 8;
        cpasync16(&hsm[BS_OFF(row, kc)], Bp + (size_t)(bn0 + row) * 256 + kc);
    }
    asm volatile("cp.async.commit_group;\n");
    ISSUE_A(0, 0);
    ISSUE_A(1, 1);

    float acc[4][4][4];
#pragma unroll
    for (int i = 0; i < 4; i++)
#pragma unroll
        for (int j = 0; j < 4; j++)
#pragma unroll
            for (int e = 0; e < 4; e++) acc[i][j][e] = 0.0f;

#pragma unroll
    for (int kt = 0; kt < 8; kt++) {
        int st = kt % 3;
        if (kt < 7) { asm volatile("cp.async.wait_group 1;\n"); }
        else        { asm volatile("cp.async.wait_group 0;\n"); }
        __syncthreads();
        if (kt + 2 < 8) ISSUE_A((kt + 2) % 3, kt + 2);

        uint32_t af[2][4][4], bf[2][4][2];
        LOAD_FRAGS(0, st, kt * 32, 0);
#pragma unroll
        for (int ksq = 0; ksq < 2; ksq++) {
            int cur = ksq & 1;
            if (ksq == 0) LOAD_FRAGS(1, st, kt * 32, 16);
#pragma unroll
            for (int mt = 0; mt < 4; mt++)
#pragma unroll
                for (int nt = 0; nt < 4; nt++)
                    mma_f16(acc[mt][nt], af[cur][mt], bf[cur][nt]);
        }
    }

    // epilogue
#pragma unroll
    for (int mt = 0; mt < 4; mt++) {
#pragma unroll
        for (int nt = 0; nt < 4; nt++) {
            int n = bn0 + wn + nt * 8 + 2 * tig;
            float b0 = biasp[n], b1 = biasp[n + 1];
#pragma unroll
            for (int half_i = 0; half_i < 2; half_i++) {
                int m = bm0 + wm + mt * 16 + gid + half_i * 8;
                float v0 = acc[mt][nt][half_i * 2]     + b0;
                float v1 = acc[mt][nt][half_i * 2 + 1] + b1;
                if (mode == 0) {
                    int part = n >> 8, cc = n & 255;
                    int head = cc >> 5, d = cc & 31;
                    int b = m >> 6, tok = m & 63;
                    if (part == 0) { v0 *= SCALE_Q; v1 *= SCALE_Q; }
                    __half* dst = (part == 0) ? g_qh : ((part == 1) ? g_kh : g_vh);
                    __half2 h = __floats2half2_rn(v0, v1);
                    *(__half2*)&dst[(((size_t)(b * NHEAD + head)) * NTOK + tok) * HD + d] = h;
                } else {
                    float2 r2; r2.x = v0; r2.y = v1;
                    *(float2*)&out[(size_t)m * CH + n] = r2;
                }
            }
        }
    }
}

// ---------------- attention: single-exp, no-max softmax, trans-ldmatrix V ----
__global__ __launch_bounds__(128) void attn_kernel(
    const float* __restrict__ rel_table, const float* __restrict__ ego_table,
    const float* __restrict__ wvec)
{
    __shared__ __half sQK[2 * NTOK * 40];   // sq then sk; sP (64x72=4608) overlays (5120)
    __shared__ __half sv[NTOK * 40];        // V row-major [m][d], stride 40
    __shared__ float  srel[225];

    __half* sq = sQK;
    __half* sk = sQK + NTOK * 40;

    int bh = blockIdx.x;
    int b = bh >> 3, head = bh & 7;
    int tid = threadIdx.x, warp = tid >> 5, lane = tid & 31;
    int gid = lane >> 2, tig = lane & 3;
    int wm = warp * 16;
    size_t base = (size_t)bh * (NTOK * HD);

    int n0 = wm + gid, n1 = wm + gid + 8;

    uint32_t sqB = (uint32_t)__cvta_generic_to_shared(sq);
    uint32_t skB = (uint32_t)__cvta_generic_to_shared(sk);
    uint32_t svB = (uint32_t)__cvta_generic_to_shared(sv);
    uint32_t sPB = sqB;   // overlay

    int aRow = lane & 15;
    int aCol = (lane >> 4) * 8;
    int bRow = ((lane >> 4) << 3) + (lane & 7);
    int bCol = ((lane >> 3) & 1) * 8;
    // trans-ldmatrix lane mapping: row within [k][n] tile, col group
    int trRow = ((lane >> 3) & 1) * 8 + (lane & 7);
    int trCol = (lane >> 4) * 8;

    // tiles: 64 rows x 32 halfs = 256 uint4 groups; all vectorized
#pragma unroll
    for (int i = 0; i < 2; i++) {
        int v = tid + i * 128;
        int row = v >> 2, c8 = (v & 3) * 8;
        *(uint4*)&sq[row * 40 + c8] = *(const uint4*)(g_qh + base + row * HD + c8);
        *(uint4*)&sk[row * 40 + c8] = *(const uint4*)(g_kh + base + row * HD + c8);
        *(uint4*)&sv[row * 40 + c8] = *(const uint4*)(g_vh + base + row * HD + c8);
    }
    for (int i = tid; i < 225; i += 128) srel[i] = rel_table[i * NHEAD + head];
    __syncthreads();

    // ---- S = q @ k^T ----
    float sacc[8][4];
#pragma unroll
    for (int nt = 0; nt < 8; nt++)
#pragma unroll
        for (int e = 0; e < 4; e++) sacc[nt][e] = 0.0f;

#pragma unroll
    for (int ksi = 0; ksi < 2; ksi++) {
        uint32_t qf[4], bf[8][2];
        ldsm4(qf[0], qf[1], qf[2], qf[3],
              sqB + ((wm + aRow) * 40 + ksi*16 + aCol) * 2);
#pragma unroll
        for (int p = 0; p < 4; p++)
            ldsm4(bf[2*p][0], bf[2*p][1], bf[2*p+1][0], bf[2*p+1][1],
                  skB + ((p*16 + bRow) * 40 + ksi*16 + bCol) * 2);
#pragma unroll
        for (int nt = 0; nt < 8; nt++) mma_f16(sacc[nt], qf, bf[nt]);
    }

    // biases
    float ego_b = ego_table[g_egoidx[b] * NHEAD + head];
    int ny0 = n0 >> 3, nx0 = n0 & 7, ny1 = n1 >> 3, nx1 = n1 & 7;
#pragma unroll
    for (int nt = 0; nt < 8; nt++) {
#pragma unroll
        for (int e = 0; e < 4; e++) {
            int mm = nt * 8 + 2 * tig + (e & 1);
            int my = mm >> 3, mx = mm & 7;
            int ny = (e < 2) ? ny0 : ny1, nx = (e < 2) ? nx0 : nx1;
            sacc[nt][e] += srel[(ny - my + 7) * 15 + (nx - mx + 7)] + ego_b;
        }
    }

    // mixing weights
    float w0 = wvec[0], w1 = wvec[1];
    float mw = fmaxf(w0, w1);
    float e0w = __expf(w0 - mw), e1w = __expf(w1 - mw);
    float inv_w = 1.0f / (e0w + e1w);
    float ws0 = e0w * inv_w, ws1 = e1w * inv_w;

    // ---- softmax, no max-shift (|s| <~ 2 by construction), single exp ----
    float sum0 = 0.0f, sum1 = 0.0f;
    uint32_t ph0[8], ph1[8];     // exp(s) packed fp16x2
#pragma unroll
    for (int nt = 0; nt < 8; nt++) {
        float e0 = __expf(sacc[nt][0]);
        float e1 = __expf(sacc[nt][1]);
        float e2 = __expf(sacc[nt][2]);
        float e3 = __expf(sacc[nt][3]);
        sum0 += e0 + e1;
        sum1 += e2 + e3;
        __half2 h0 = __floats2half2_rn(e0, e1);
        __half2 h1 = __floats2half2_rn(e2, e3);
        ph0[nt] = *(uint32_t*)&h0;
        ph1[nt] = *(uint32_t*)&h1;
    }
    sum0 += __shfl_xor_sync(0xffffffffu, sum0, 1);
    sum0 += __shfl_xor_sync(0xffffffffu, sum0, 2);
    sum1 += __shfl_xor_sync(0xffffffffu, sum1, 1);
    sum1 += __shfl_xor_sync(0xffffffffu, sum1, 2);
    float i0 = ws0 / sum0, i1 = ws0 / sum1;   // fold ws0 into normalizer

    __syncthreads();   // all warps done reading sq/sk -> safe to overlay sP

#pragma unroll
    for (int nt = 0; nt < 8; nt++) {
        float2 e01 = __half22float2(*(__half2*)&ph0[nt]);
        float2 e23 = __half22float2(*(__half2*)&ph1[nt]);
        float r0a = fmaxf(sacc[nt][0], 0.0f), r0b = fmaxf(sacc[nt][1], 0.0f);
        float r1a = fmaxf(sacc[nt][2], 0.0f), r1b = fmaxf(sacc[nt][3], 0.0f);
        __half2 P0 = __floats2half2_rn(i0 * e01.x + ws1 * r0a * r0a,
                                       i0 * e01.y + ws1 * r0b * r0b);
        __half2 P1 = __floats2half2_rn(i1 * e23.x + ws1 * r1a * r1a,
                                       i1 * e23.y + ws1 * r1b * r1b);
        *(__half2*)&sQK[n0 * 72 + nt * 8 + 2 * tig] = P0;
        *(__half2*)&sQK[n1 * 72 + nt * 8 + 2 * tig] = P1;
    }
    __syncwarp();      // each warp only reads its own sP rows below

    // ---- O = P @ V : vf via trans-ldmatrix straight from row-major V ----
    float oacc[4][4];
#pragma unroll
    for (int nt = 0; nt < 4; nt++)
#pragma unroll
        for (int e = 0; e < 4; e++) oacc[nt][e] = 0.0f;

#pragma unroll
    for (int ksi = 0; ksi < 4; ksi++) {
        uint32_t pf[4], vf[4][2];
        ldsm4(pf[0], pf[1], pf[2], pf[3],
              sPB + ((wm + aRow) * 72 + ksi*16 + aCol) * 2);
#pragma unroll
        for (int pp = 0; pp < 2; pp++)
            ldsm4t(vf[2*pp][0], vf[2*pp][1], vf[2*pp+1][0], vf[2*pp+1][1],
                   svB + ((ksi*16 + trRow) * 40 + pp*16 + trCol) * 2);
#pragma unroll
        for (int nt = 0; nt < 4; nt++) mma_f16(oacc[nt], pf, vf[nt]);
    }

    __half* aop = g_aoh + (size_t)(b * NTOK) * CH + head * HD;
#pragma unroll
    for (int nt = 0; nt < 4; nt++) {
        int d0 = nt * 8 + 2 * tig;
        __half2 s0 = __floats2half2_rn(oacc[nt][0], oacc[nt][1]);
        __half2 s1 = __floats2half2_rn(oacc[nt][2], oacc[nt][3]);
        *(__half2*)(aop + (size_t)n0 * CH + d0) = s0;
        *(__half2*)(aop + (size_t)n1 * CH + d0) = s1;
    }
}

// ---------------- launch ----------------
extern "C" void kernel_launch(void* const* d_in, const int* in_sizes, int n_in,
                              void* d_out, int out_size) {
    const float* x    = (const float*)d_in[0];
    const float* aff  = (const float*)d_in[1];
    const float* Wq   = (const float*)d_in[2];
    const float* bq   = (const float*)d_in[3];
    const float* Wkv  = (const float*)d_in[4];
    const float* bkv  = (const float*)d_in[5];
    const float* Wp   = (const float*)d_in[6];
    const float* bp   = (const float*)d_in[7];
    const float* rel  = (const float*)d_in[8];
    const float* ego  = (const float*)d_in[9];
    const float* w    = (const float*)d_in[10];
    float* out = (float*)d_out;

    const int GEMM_SMEM = (128*264 + 3*128*40) * 2;   // 98304 B -> 2 CTAs/SM
    static int attr_set = 0;
    if (!attr_set) {
        cudaFuncSetAttribute(gemm_f16, cudaFuncAttributeMaxDynamicSharedMemorySize, GEMM_SMEM);
        attr_set = 1;
    }

    pack_kernel<<<768, 256>>>(Wq, bq, Wkv, bkv, Wp);
    ego_kernel<<<1, 256>>>(aff);
    prep_x<<<16384, 256>>>(x);
    gemm_f16<<<dim3(6, 1024), 256, GEMM_SMEM>>>(nullptr, 0, nullptr);
    attn_kernel<<<BWIN * NHEAD, 128>>>(rel, ego, w);
    gemm_f16<<<dim3(2, 1024), 256, GEMM_SMEM>>>(bp, 1, out);
}

// round 15
// speedup vs baseline: 1.0247x; 1.0247x over previous
#include <cuda_runtime.h>
#include <cuda_fp16.h>
#include <cstdint>
#include <cstddef>

// ---------------- problem constants ----------------
#define NCAV     2
#define WIN      8
#define BWIN     2048
#define NTOK     64
#define CH       256
#define NHEAD    8
#define HD       32
#define MROWS    (BWIN*NTOK)    // 131072
#define SCALE_Q  0.17677669529663687f
#define PI_F     3.14159274101257324f

// ---------------- scratch (fp16 pipeline) ----------------
__device__ __half g_xh  [(size_t)MROWS*CH];       // x, fp16
__device__ __half g_qh  [BWIN*NHEAD*NTOK*HD];
__device__ __half g_kh  [BWIN*NHEAD*NTOK*HD];
__device__ __half g_vh  [BWIN*NHEAD*NTOK*HD];
__device__ __half g_aoh [(size_t)MROWS*CH];       // attn output, fp16
__device__ __half g_wqkvh[768*CH];                // [n][k] transposed fp16
__device__ __half g_wph [CH*CH];                  // [n][k] transposed fp16
__device__ float  g_bqkv[768];
__device__ int    g_egoidx[BWIN];

// ---------------- helpers ----------------
__device__ __forceinline__ void mma_f16(float c[4], const uint32_t a[4], const uint32_t b[2]) {
    asm volatile(
        "mma.sync.aligned.m16n8k16.row.col.f32.f16.f16.f32 "
        "{%0,%1,%2,%3},{%4,%5,%6,%7},{%8,%9},{%0,%1,%2,%3};\n"
        : "+f"(c[0]), "+f"(c[1]), "+f"(c[2]), "+f"(c[3])
        : "r"(a[0]), "r"(a[1]), "r"(a[2]), "r"(a[3]), "r"(b[0]), "r"(b[1]));
}

__device__ __forceinline__ void ldsm4(uint32_t& r0, uint32_t& r1, uint32_t& r2, uint32_t& r3,
                                      uint32_t saddr) {
    asm volatile("ldmatrix.sync.aligned.m8n8.x4.shared.b16 {%0,%1,%2,%3}, [%4];\n"
                 : "=r"(r0), "=r"(r1), "=r"(r2), "=r"(r3) : "r"(saddr));
}

__device__ __forceinline__ void ldsm4t(uint32_t& r0, uint32_t& r1, uint32_t& r2, uint32_t& r3,
                                       uint32_t saddr) {
    asm volatile("ldmatrix.sync.aligned.m8n8.x4.trans.shared.b16 {%0,%1,%2,%3}, [%4];\n"
                 : "=r"(r0), "=r"(r1), "=r"(r2), "=r"(r3) : "r"(saddr));
}

__device__ __forceinline__ void cpasync16(void* s, const void* g) {
    uint32_t sa = (uint32_t)__cvta_generic_to_shared(s);
    asm volatile("cp.async.cg.shared.global [%0], [%1], 16;\n" :: "r"(sa), "l"(g));
}

// ---------------- fused prep: prep_x | pack | ego, branch on blockIdx ----------
// grid = 16384 (prep_x) + 768 (pack) + 1 (ego), 256 threads
__global__ void prep_kernel(const float* __restrict__ x,
                            const float* __restrict__ Wq, const float* __restrict__ bq,
                            const float* __restrict__ Wkv, const float* __restrict__ bkv,
                            const float* __restrict__ Wp, const float* __restrict__ A) {
    int blk = blockIdx.x;
    int tid = threadIdx.x;
    if (blk < 16384) {
        // ---- prep_x ----
        size_t i = ((size_t)blk * 256 + tid) * 8;
        float4 a = *(const float4*)(x + i);
        float4 b = *(const float4*)(x + i + 4);
        __half2 h[4];
        h[0] = __floats2half2_rn(a.x, a.y);
        h[1] = __floats2half2_rn(a.z, a.w);
        h[2] = __floats2half2_rn(b.x, b.y);
        h[3] = __floats2half2_rn(b.z, b.w);
        *(uint4*)(g_xh + i) = *(uint4*)h;
    } else if (blk < 16384 + 768) {
        // ---- pack weights transposed [n][k] fp16 ----
        int t = (blk - 16384) * 256 + tid;
        int n = t >> 8, k = t & 255;
        g_wqkvh[t] = __float2half_rn((n < CH) ? Wq[k*CH + n] : Wkv[k*512 + (n - CH)]);
        if (t < 768) g_bqkv[t] = (t < CH) ? bq[t] : bkv[t - CH];
        if (t < CH*CH) g_wph[t] = __float2half_rn(Wp[k*CH + n]);
    } else {
        // ---- ego bias bin index ----
        __shared__ float rx[BWIN], ry[BWIN];
        __shared__ float red[256];
        float ex[NCAV], ey[NCAV];
#pragma unroll
        for (int c = 0; c < NCAV; c++) {
            ex[c] = A[c*6 + 0] * 128.0f + A[c*6 + 1] * 128.0f + A[c*6 + 2];
            ey[c] = A[c*6 + 3] * 128.0f + A[c*6 + 4] * 128.0f + A[c*6 + 5];
        }
        float lmax = 0.0f;
        for (int i = tid; i < BWIN; i += 256) {
            int cav = i >> 10, wi = i & 1023;
            int gy = wi >> 5, gx = wi & 31;
            float cx = gx * (float)WIN + WIN * 0.5f;
            float cy = gy * (float)WIN + WIN * 0.5f;
            float rxx = cx - ex[cav], ryy = cy - ey[cav];
            rx[i] = rxx; ry[i] = ryy;
            lmax = fmaxf(lmax, sqrtf(rxx*rxx + ryy*ryy));
        }
        red[tid] = lmax;
        __syncthreads();
        for (int s = 128; s > 0; s >>= 1) {
            if (tid < s) red[tid] = fmaxf(red[tid], red[tid + s]);
            __syncthreads();
        }
        float maxd = red[0] + 1e-6f;
        for (int i = tid; i < BWIN; i += 256) {
            float rxx = rx[i], ryy = ry[i];
            float d = sqrtf(rxx*rxx + ryy*ryy);
            int db = (int)(d / maxd * 3.0f);
            float ang = atan2f(ryy, rxx);
            int ab = (int)((ang + PI_F) / (2.0f * PI_F) * 3.0f);
            g_egoidx[i] = db * 4 + ab;
        }
    }
}

// ---------------- GEMM fp16: resident B + 2-stage k64 streamed A ----------
// C[M,N] = A[M,256] @ B^T + bias, B [n][k] fp16.
// smem halfs: Bs[128][264] = 33792 ; As[2][128][72] = 18432 ; total 52224 (102KB)
#define BS_OFF(r, c)      ((r)*264 + (c))
#define AS_OFF(st, r, c)  (33792 + (st)*9216 + (r)*72 + (c))

#define ISSUE_A(st, kt) do {                                                  \
    _Pragma("unroll")                                                         \
    for (int ii = 0; ii < 4; ii++) {                                          \
        int c = tid + ii * 256;                                               \
        int row = c >> 3, kc = (c & 7) * 8;                                   \
        cpasync16(&hsm[AS_OFF(st, row, kc)],                                  \
                  Ap + (size_t)(bm0 + row) * 256 + (kt) * 64 + kc);           \
    }                                                                         \
    asm volatile("cp.async.commit_group;\n");                                 \
} while (0)

#define LOAD_FRAGS(buf, st, kglob, ks) do {                                   \
    _Pragma("unroll")                                                         \
    for (int mt = 0; mt < 4; mt++)                                            \
        ldsm4(af[buf][mt][0], af[buf][mt][1], af[buf][mt][2], af[buf][mt][3], \
              smemBase + AS_OFF(st, wm + mt*16 + aRow, (ks) + aCol) * 2);     \
    _Pragma("unroll")                                                         \
    for (int p = 0; p < 2; p++)                                               \
        ldsm4(bf[buf][2*p][0], bf[buf][2*p][1], bf[buf][2*p+1][0], bf[buf][2*p+1][1], \
              smemBase + BS_OFF(wn + p*16 + bRow, (kglob) + (ks) + bCol) * 2);\
} while (0)

__global__ __launch_bounds__(256, 2) void gemm_f16(
    const float* __restrict__ bias_ext, int mode, float* __restrict__ out)
{
    extern __shared__ __half hsm[];
    const __half* __restrict__ Ap    = (mode == 0) ? g_xh : g_aoh;
    const __half* __restrict__ Bp    = (mode == 0) ? g_wqkvh : g_wph;
    const float*  __restrict__ biasp = (mode == 0) ? g_bqkv : bias_ext;

    const int bm0 = blockIdx.y * 128;
    const int bn0 = blockIdx.x * 128;
    int tid = threadIdx.x, warp = tid >> 5, lane = tid & 31;
    int wm = (warp & 1) * 64, wn = (warp >> 1) * 32;
    int gid = lane >> 2, tig = lane & 3;

    uint32_t smemBase = (uint32_t)__cvta_generic_to_shared(hsm);
    int aRow = lane & 15;
    int aCol = (lane >> 4) * 8;
    int bRow = ((lane >> 4) << 3) + (lane & 7);
    int bCol = ((lane >> 3) & 1) * 8;

    // prologue: resident B tile, then A stage 0 (k64)
#pragma unroll
    for (int ii = 0; ii < 16; ii++) {
        int c = tid + ii * 256;
        int row = c >> 5, kc = (c & 31) * 8;
        cpasync16(&hsm[BS_OFF(row, kc)], Bp + (size_t)(bn0 + row) * 256 + kc);
    }
    asm volatile("cp.async.commit_group;\n");
    ISSUE_A(0, 0);

    float acc[4][4][4];
#pragma unroll
    for (int i = 0; i < 4; i++)
#pragma unroll
        for (int j = 0; j < 4; j++)
#pragma unroll
            for (int e = 0; e < 4; e++) acc[i][j][e] = 0.0f;

#pragma unroll
    for (int kt = 0; kt < 4; kt++) {
        int st = kt & 1;
        asm volatile("cp.async.wait_group 0;\n");   // stage kt (and B on kt=0) landed
        __syncthreads();                            // frees stage st^1 for reuse
        if (kt + 1 < 4) ISSUE_A(st ^ 1, kt + 1);    // overlaps compute below

        uint32_t af[2][4][4], bf[2][4][2];
        LOAD_FRAGS(0, st, kt * 64, 0);
#pragma unroll
        for (int ksq = 0; ksq < 4; ksq++) {         // four k16 steps per 64-k tile
            int cur = ksq & 1;
            if (ksq < 3) LOAD_FRAGS(cur ^ 1, st, kt * 64, (ksq + 1) * 16);
#pragma unroll
            for (int mt = 0; mt < 4; mt++)
#pragma unroll
                for (int nt = 0; nt < 4; nt++)
                    mma_f16(acc[mt][nt], af[cur][mt], bf[cur][nt]);
        }
    }

    // epilogue
#pragma unroll
    for (int mt = 0; mt < 4; mt++) {
#pragma unroll
        for (int nt = 0; nt < 4; nt++) {
            int n = bn0 + wn + nt * 8 + 2 * tig;
            float b0 = biasp[n], b1 = biasp[n + 1];
#pragma unroll
            for (int half_i = 0; half_i < 2; half_i++) {
                int m = bm0 + wm + mt * 16 + gid + half_i * 8;
                float v0 = acc[mt][nt][half_i * 2]     + b0;
                float v1 = acc[mt][nt][half_i * 2 + 1] + b1;
                if (mode == 0) {
                    int part = n >> 8, cc = n & 255;
                    int head = cc >> 5, d = cc & 31;
                    int b = m >> 6, tok = m & 63;
                    if (part == 0) { v0 *= SCALE_Q; v1 *= SCALE_Q; }
                    __half* dst = (part == 0) ? g_qh : ((part == 1) ? g_kh : g_vh);
                    __half2 h = __floats2half2_rn(v0, v1);
                    *(__half2*)&dst[(((size_t)(b * NHEAD + head)) * NTOK + tok) * HD + d] = h;
                } else {
                    float2 r2; r2.x = v0; r2.y = v1;
                    *(float2*)&out[(size_t)m * CH + n] = r2;
                }
            }
        }
    }
}

// ---------------- attention: single-exp, no-max softmax, trans-ldmatrix V ----
__global__ __launch_bounds__(128) void attn_kernel(
    const float* __restrict__ rel_table, const float* __restrict__ ego_table,
    const float* __restrict__ wvec)
{
    __shared__ __half sQK[2 * NTOK * 40];   // sq then sk; sP (64x72=4608) overlays (5120)
    __shared__ __half sv[NTOK * 40];        // V row-major [m][d], stride 40
    __shared__ float  srel[225];

    __half* sq = sQK;
    __half* sk = sQK + NTOK * 40;

    int bh = blockIdx.x;
    int b = bh >> 3, head = bh & 7;
    int tid = threadIdx.x, warp = tid >> 5, lane = tid & 31;
    int gid = lane >> 2, tig = lane & 3;
    int wm = warp * 16;
    size_t base = (size_t)bh * (NTOK * HD);

    int n0 = wm + gid, n1 = wm + gid + 8;

    uint32_t sqB = (uint32_t)__cvta_generic_to_shared(sq);
    uint32_t skB = (uint32_t)__cvta_generic_to_shared(sk);
    uint32_t svB = (uint32_t)__cvta_generic_to_shared(sv);
    uint32_t sPB = sqB;   // overlay

    int aRow = lane & 15;
    int aCol = (lane >> 4) * 8;
    int bRow = ((lane >> 4) << 3) + (lane & 7);
    int bCol = ((lane >> 3) & 1) * 8;
    int trRow = ((lane >> 3) & 1) * 8 + (lane & 7);
    int trCol = (lane >> 4) * 8;

#pragma unroll
    for (int i = 0; i < 2; i++) {
        int v = tid + i * 128;
        int row = v >> 2, c8 = (v & 3) * 8;
        *(uint4*)&sq[row * 40 + c8] = *(const uint4*)(g_qh + base + row * HD + c8);
        *(uint4*)&sk[row * 40 + c8] = *(const uint4*)(g_kh + base + row * HD + c8);
        *(uint4*)&sv[row * 40 + c8] = *(const uint4*)(g_vh + base + row * HD + c8);
    }
    for (int i = tid; i < 225; i += 128) srel[i] = rel_table[i * NHEAD + head];
    __syncthreads();

    // ---- S = q @ k^T ----
    float sacc[8][4];
#pragma unroll
    for (int nt = 0; nt < 8; nt++)
#pragma unroll
        for (int e = 0; e < 4; e++) sacc[nt][e] = 0.0f;

#pragma unroll
    for (int ksi = 0; ksi < 2; ksi++) {
        uint32_t qf[4], bf[8][2];
        ldsm4(qf[0], qf[1], qf[2], qf[3],
              sqB + ((wm + aRow) * 40 + ksi*16 + aCol) * 2);
#pragma unroll
        for (int p = 0; p < 4; p++)
            ldsm4(bf[2*p][0], bf[2*p][1], bf[2*p+1][0], bf[2*p+1][1],
                  skB + ((p*16 + bRow) * 40 + ksi*16 + bCol) * 2);
#pragma unroll
        for (int nt = 0; nt < 8; nt++) mma_f16(sacc[nt], qf, bf[nt]);
    }

    // biases
    float ego_b = ego_table[g_egoidx[b] * NHEAD + head];
    int ny0 = n0 >> 3, nx0 = n0 & 7, ny1 = n1 >> 3, nx1 = n1 & 7;
#pragma unroll
    for (int nt = 0; nt < 8; nt++) {
#pragma unroll
        for (int e = 0; e < 4; e++) {
            int mm = nt * 8 + 2 * tig + (e & 1);
            int my = mm >> 3, mx = mm & 7;
            int ny = (e < 2) ? ny0 : ny1, nx = (e < 2) ? nx0 : nx1;
            sacc[nt][e] += srel[(ny - my + 7) * 15 + (nx - mx + 7)] + ego_b;
        }
    }

    // mixing weights
    float w0 = wvec[0], w1 = wvec[1];
    float mw = fmaxf(w0, w1);
    float e0w = __expf(w0 - mw), e1w = __expf(w1 - mw);
    float inv_w = 1.0f / (e0w + e1w);
    float ws0 = e0w * inv_w, ws1 = e1w * inv_w;

    // ---- softmax, no max-shift, single exp (packed fp16) ----
    float sum0 = 0.0f, sum1 = 0.0f;
    uint32_t ph0[8], ph1[8];
#pragma unroll
    for (int nt = 0; nt < 8; nt++) {
        float e0 = __expf(sacc[nt][0]);
        float e1 = __expf(sacc[nt][1]);
        float e2 = __expf(sacc[nt][2]);
        float e3 = __expf(sacc[nt][3]);
        sum0 += e0 + e1;
        sum1 += e2 + e3;
        __half2 h0 = __floats2half2_rn(e0, e1);
        __half2 h1 = __floats2half2_rn(e2, e3);
        ph0[nt] = *(uint32_t*)&h0;
        ph1[nt] = *(uint32_t*)&h1;
    }
    sum0 += __shfl_xor_sync(0xffffffffu, sum0, 1);
    sum0 += __shfl_xor_sync(0xffffffffu, sum0, 2);
    sum1 += __shfl_xor_sync(0xffffffffu, sum1, 1);
    sum1 += __shfl_xor_sync(0xffffffffu, sum1, 2);
    float i0 = ws0 / sum0, i1 = ws0 / sum1;

    __syncthreads();   // all warps done reading sq/sk -> safe to overlay sP

#pragma unroll
    for (int nt = 0; nt < 8; nt++) {
        float2 e01 = __half22float2(*(__half2*)&ph0[nt]);
        float2 e23 = __half22float2(*(__half2*)&ph1[nt]);
        float r0a = fmaxf(sacc[nt][0], 0.0f), r0b = fmaxf(sacc[nt][1], 0.0f);
        float r1a = fmaxf(sacc[nt][2], 0.0f), r1b = fmaxf(sacc[nt][3], 0.0f);
        __half2 P0 = __floats2half2_rn(i0 * e01.x + ws1 * r0a * r0a,
                                       i0 * e01.y + ws1 * r0b * r0b);
        __half2 P1 = __floats2half2_rn(i1 * e23.x + ws1 * r1a * r1a,
                                       i1 * e23.y + ws1 * r1b * r1b);
        *(__half2*)&sQK[n0 * 72 + nt * 8 + 2 * tig] = P0;
        *(__half2*)&sQK[n1 * 72 + nt * 8 + 2 * tig] = P1;
    }
    __syncwarp();

    // ---- O = P @ V : vf via trans-ldmatrix from row-major V ----
    float oacc[4][4];
#pragma unroll
    for (int nt = 0; nt < 4; nt++)
#pragma unroll
        for (int e = 0; e < 4; e++) oacc[nt][e] = 0.0f;

#pragma unroll
    for (int ksi = 0; ksi < 4; ksi++) {
        uint32_t pf[4], vf[4][2];
        ldsm4(pf[0], pf[1], pf[2], pf[3],
              sPB + ((wm + aRow) * 72 + ksi*16 + aCol) * 2);
#pragma unroll
        for (int pp = 0; pp < 2; pp++)
            ldsm4t(vf[2*pp][0], vf[2*pp][1], vf[2*pp+1][0], vf[2*pp+1][1],
                   svB + ((ksi*16 + trRow) * 40 + pp*16 + trCol) * 2);
#pragma unroll
        for (int nt = 0; nt < 4; nt++) mma_f16(oacc[nt], pf, vf[nt]);
    }

    __half* aop = g_aoh + (size_t)(b * NTOK) * CH + head * HD;
#pragma unroll
    for (int nt = 0; nt < 4; nt++) {
        int d0 = nt * 8 + 2 * tig;
        __half2 s0 = __floats2half2_rn(oacc[nt][0], oacc[nt][1]);
        __half2 s1 = __floats2half2_rn(oacc[nt][2], oacc[nt][3]);
        *(__half2*)(aop + (size_t)n0 * CH + d0) = s0;
        *(__half2*)(aop + (size_t)n1 * CH + d0) = s1;
    }
}

// ---------------- launch ----------------
extern "C" void kernel_launch(void* const* d_in, const int* in_sizes, int n_in,
                              void* d_out, int out_size) {
    const float* x    = (const float*)d_in[0];
    const float* aff  = (const float*)d_in[1];
    const float* Wq   = (const float*)d_in[2];
    const float* bq   = (const float*)d_in[3];
    const float* Wkv  = (const float*)d_in[4];
    const float* bkv  = (const float*)d_in[5];
    const float* Wp   = (const float*)d_in[6];
    const float* bp   = (const float*)d_in[7];
    const float* rel  = (const float*)d_in[8];
    const float* ego  = (const float*)d_in[9];
    const float* w    = (const float*)d_in[10];
    float* out = (float*)d_out;

    const int GEMM_SMEM = (33792 + 2 * 9216) * 2;   // 104448 B -> 2 CTAs/SM
    static int attr_set = 0;
    if (!attr_set) {
        cudaFuncSetAttribute(gemm_f16, cudaFuncAttributeMaxDynamicSharedMemorySize, GEMM_SMEM);
        attr_set = 1;
    }

    prep_kernel<<<16384 + 768 + 1, 256>>>(x, Wq, bq, Wkv, bkv, Wp, aff);
    gemm_f16<<<dim3(6, 1024), 256, GEMM_SMEM>>>(nullptr, 0, nullptr);
    attn_kernel<<<BWIN * NHEAD, 128>>>(rel, ego, w);
    gemm_f16<<<dim3(2, 1024), 256, GEMM_SMEM>>>(bp, 1, out);
}

// round 16
// speedup vs baseline: 1.0530x; 1.0277x over previous
#include <cuda_runtime.h>
#include <cuda_fp16.h>
#include <cstdint>
#include <cstddef>

// ---------------- problem constants ----------------
#define NCAV     2
#define WIN      8
#define BWIN     2048
#define NTOK     64
#define CH       256
#define NHEAD    8
#define HD       32
#define MROWS    (BWIN*NTOK)    // 131072
#define SCALE_Q  0.17677669529663687f
#define PI_F     3.14159274101257324f

// ---------------- scratch (fp16 pipeline) ----------------
__device__ __half g_xh  [(size_t)MROWS*CH];       // x, fp16
__device__ __half g_qh  [BWIN*NHEAD*NTOK*HD];
__device__ __half g_kh  [BWIN*NHEAD*NTOK*HD];
__device__ __half g_vh  [BWIN*NHEAD*NTOK*HD];
__device__ __half g_aoh [(size_t)MROWS*CH];       // attn output, fp16
__device__ __half g_wqkvh[768*CH];                // [n][k] transposed fp16
__device__ __half g_wph [CH*CH];                  // [n][k] transposed fp16
__device__ float  g_bqkv[768];
__device__ int    g_egoidx[BWIN];

// ---------------- helpers ----------------
__device__ __forceinline__ void mma_f16(float c[4], const uint32_t a[4], const uint32_t b[2]) {
    asm volatile(
        "mma.sync.aligned.m16n8k16.row.col.f32.f16.f16.f32 "
        "{%0,%1,%2,%3},{%4,%5,%6,%7},{%8,%9},{%0,%1,%2,%3};\n"
        : "+f"(c[0]), "+f"(c[1]), "+f"(c[2]), "+f"(c[3])
        : "r"(a[0]), "r"(a[1]), "r"(a[2]), "r"(a[3]), "r"(b[0]), "r"(b[1]));
}

__device__ __forceinline__ void ldsm4(uint32_t& r0, uint32_t& r1, uint32_t& r2, uint32_t& r3,
                                      uint32_t saddr) {
    asm volatile("ldmatrix.sync.aligned.m8n8.x4.shared.b16 {%0,%1,%2,%3}, [%4];\n"
                 : "=r"(r0), "=r"(r1), "=r"(r2), "=r"(r3) : "r"(saddr));
}

__device__ __forceinline__ void ldsm4t(uint32_t& r0, uint32_t& r1, uint32_t& r2, uint32_t& r3,
                                       uint32_t saddr) {
    asm volatile("ldmatrix.sync.aligned.m8n8.x4.trans.shared.b16 {%0,%1,%2,%3}, [%4];\n"
                 : "=r"(r0), "=r"(r1), "=r"(r2), "=r"(r3) : "r"(saddr));
}

__device__ __forceinline__ void cpasync16(void* s, const void* g) {
    uint32_t sa = (uint32_t)__cvta_generic_to_shared(s);
    asm volatile("cp.async.cg.shared.global [%0], [%1], 16;\n" :: "r"(sa), "l"(g));
}

// ---------------- fused prep: prep_x | pack | ego, branch on blockIdx ----------
__global__ void prep_kernel(const float* __restrict__ x,
                            const float* __restrict__ Wq, const float* __restrict__ bq,
                            const float* __restrict__ Wkv, const float* __restrict__ bkv,
                            const float* __restrict__ Wp, const float* __restrict__ A) {
    int blk = blockIdx.x;
    int tid = threadIdx.x;
    if (blk < 16384) {
        size_t i = ((size_t)blk * 256 + tid) * 8;
        float4 a = *(const float4*)(x + i);
        float4 b = *(const float4*)(x + i + 4);
        __half2 h[4];
        h[0] = __floats2half2_rn(a.x, a.y);
        h[1] = __floats2half2_rn(a.z, a.w);
        h[2] = __floats2half2_rn(b.x, b.y);
        h[3] = __floats2half2_rn(b.z, b.w);
        *(uint4*)(g_xh + i) = *(uint4*)h;
    } else if (blk < 16384 + 768) {
        int t = (blk - 16384) * 256 + tid;
        int n = t >> 8, k = t & 255;
        g_wqkvh[t] = __float2half_rn((n < CH) ? Wq[k*CH + n] : Wkv[k*512 + (n - CH)]);
        if (t < 768) g_bqkv[t] = (t < CH) ? bq[t] : bkv[t - CH];
        if (t < CH*CH) g_wph[t] = __float2half_rn(Wp[k*CH + n]);
    } else {
        __shared__ float rx[BWIN], ry[BWIN];
        __shared__ float red[256];
        float ex[NCAV], ey[NCAV];
#pragma unroll
        for (int c = 0; c < NCAV; c++) {
            ex[c] = A[c*6 + 0] * 128.0f + A[c*6 + 1] * 128.0f + A[c*6 + 2];
            ey[c] = A[c*6 + 3] * 128.0f + A[c*6 + 4] * 128.0f + A[c*6 + 5];
        }
        float lmax = 0.0f;
        for (int i = tid; i < BWIN; i += 256) {
            int cav = i >> 10, wi = i & 1023;
            int gy = wi >> 5, gx = wi & 31;
            float cx = gx * (float)WIN + WIN * 0.5f;
            float cy = gy * (float)WIN + WIN * 0.5f;
            float rxx = cx - ex[cav], ryy = cy - ey[cav];
            rx[i] = rxx; ry[i] = ryy;
            lmax = fmaxf(lmax, sqrtf(rxx*rxx + ryy*ryy));
        }
        red[tid] = lmax;
        __syncthreads();
        for (int s = 128; s > 0; s >>= 1) {
            if (tid < s) red[tid] = fmaxf(red[tid], red[tid + s]);
            __syncthreads();
        }
        float maxd = red[0] + 1e-6f;
        for (int i = tid; i < BWIN; i += 256) {
            float rxx = rx[i], ryy = ry[i];
            float d = sqrtf(rxx*rxx + ryy*ryy);
            int db = (int)(d / maxd * 3.0f);
            float ang = atan2f(ryy, rxx);
            int ab = (int)((ang + PI_F) / (2.0f * PI_F) * 3.0f);
            g_egoidx[i] = db * 4 + ab;
        }
    }
}

// ---------------- GEMM fp16: resident B + 2-stage k64 streamed A ----------
#define BS_OFF(r, c)      ((r)*264 + (c))
#define AS_OFF(st, r, c)  (33792 + (st)*9216 + (r)*72 + (c))

#define ISSUE_A(st, kt) do {                                                  \
    _Pragma("unroll")                                                         \
    for (int ii = 0; ii < 4; ii++) {                                          \
        int c = tid + ii * 256;                                               \
        int row = c >> 3, kc = (c & 7) * 8;                                   \
        cpasync16(&hsm[AS_OFF(st, row, kc)],                                  \
                  Ap + (size_t)(bm0 + row) * 256 + (kt) * 64 + kc);           \
    }                                                                         \
    asm volatile("cp.async.commit_group;\n");                                 \
} while (0)

#define LOAD_FRAGS(buf, st, kglob, ks) do {                                   \
    _Pragma("unroll")                                                         \
    for (int mt = 0; mt < 4; mt++)                                            \
        ldsm4(af[buf][mt][0], af[buf][mt][1], af[buf][mt][2], af[buf][mt][3], \
              smemBase + AS_OFF(st, wm + mt*16 + aRow, (ks) + aCol) * 2);     \
    _Pragma("unroll")                                                         \
    for (int p = 0; p < 2; p++)                                               \
        ldsm4(bf[buf][2*p][0], bf[buf][2*p][1], bf[buf][2*p+1][0], bf[buf][2*p+1][1], \
              smemBase + BS_OFF(wn + p*16 + bRow, (kglob) + (ks) + bCol) * 2);\
} while (0)

__global__ __launch_bounds__(256, 2) void gemm_f16(
    const float* __restrict__ bias_ext, int mode, float* __restrict__ out)
{
    extern __shared__ __half hsm[];
    const __half* __restrict__ Ap    = (mode == 0) ? g_xh : g_aoh;
    const __half* __restrict__ Bp    = (mode == 0) ? g_wqkvh : g_wph;
    const float*  __restrict__ biasp = (mode == 0) ? g_bqkv : bias_ext;

    const int bm0 = blockIdx.y * 128;
    const int bn0 = blockIdx.x * 128;
    int tid = threadIdx.x, warp = tid >> 5, lane = tid & 31;
    int wm = (warp & 1) * 64, wn = (warp >> 1) * 32;
    int gid = lane >> 2, tig = lane & 3;

    uint32_t smemBase = (uint32_t)__cvta_generic_to_shared(hsm);
    int aRow = lane & 15;
    int aCol = (lane >> 4) * 8;
    int bRow = ((lane >> 4) << 3) + (lane & 7);
    int bCol = ((lane >> 3) & 1) * 8;

#pragma unroll
    for (int ii = 0; ii < 16; ii++) {
        int c = tid + ii * 256;
        int row = c >> 5, kc = (c & 31) * 8;
        cpasync16(&hsm[BS_OFF(row, kc)], Bp + (size_t)(bn0 + row) * 256 + kc);
    }
    asm volatile("cp.async.commit_group;\n");
    ISSUE_A(0, 0);

    float acc[4][4][4];
#pragma unroll
    for (int i = 0; i < 4; i++)
#pragma unroll
        for (int j = 0; j < 4; j++)
#pragma unroll
            for (int e = 0; e < 4; e++) acc[i][j][e] = 0.0f;

#pragma unroll
    for (int kt = 0; kt < 4; kt++) {
        int st = kt & 1;
        asm volatile("cp.async.wait_group 0;\n");
        __syncthreads();
        if (kt + 1 < 4) ISSUE_A(st ^ 1, kt + 1);

        uint32_t af[2][4][4], bf[2][4][2];
        LOAD_FRAGS(0, st, kt * 64, 0);
#pragma unroll
        for (int ksq = 0; ksq < 4; ksq++) {
            int cur = ksq & 1;
            if (ksq < 3) LOAD_FRAGS(cur ^ 1, st, kt * 64, (ksq + 1) * 16);
#pragma unroll
            for (int mt = 0; mt < 4; mt++)
#pragma unroll
                for (int nt = 0; nt < 4; nt++)
                    mma_f16(acc[mt][nt], af[cur][mt], bf[cur][nt]);
        }
    }

    // epilogue
#pragma unroll
    for (int mt = 0; mt < 4; mt++) {
#pragma unroll
        for (int nt = 0; nt < 4; nt++) {
            int n = bn0 + wn + nt * 8 + 2 * tig;
            float b0 = biasp[n], b1 = biasp[n + 1];
#pragma unroll
            for (int half_i = 0; half_i < 2; half_i++) {
                int m = bm0 + wm + mt * 16 + gid + half_i * 8;
                float v0 = acc[mt][nt][half_i * 2]     + b0;
                float v1 = acc[mt][nt][half_i * 2 + 1] + b1;
                if (mode == 0) {
                    int part = n >> 8, cc = n & 255;
                    int head = cc >> 5, d = cc & 31;
                    int b = m >> 6, tok = m & 63;
                    if (part == 0) { v0 *= SCALE_Q; v1 *= SCALE_Q; }
                    __half* dst = (part == 0) ? g_qh : ((part == 1) ? g_kh : g_vh);
                    __half2 h = __floats2half2_rn(v0, v1);
                    *(__half2*)&dst[(((size_t)(b * NHEAD + head)) * NTOK + tok) * HD + d] = h;
                } else {
                    float2 r2; r2.x = v0; r2.y = v1;
                    *(float2*)&out[(size_t)m * CH + n] = r2;
                }
            }
        }
    }
}

// ---------------- attention: P kept in register fragments (no smem round-trip) ----
__global__ __launch_bounds__(128) void attn_kernel(
    const float* __restrict__ rel_table, const float* __restrict__ ego_table,
    const float* __restrict__ wvec)
{
    __shared__ __half sq[NTOK * 40];
    __shared__ __half sk[NTOK * 40];
    __shared__ __half sv[NTOK * 40];        // V row-major [m][d]
    __shared__ float  srel[225];

    int bh = blockIdx.x;
    int b = bh >> 3, head = bh & 7;
    int tid = threadIdx.x, warp = tid >> 5, lane = tid & 31;
    int gid = lane >> 2, tig = lane & 3;
    int wm = warp * 16;
    size_t base = (size_t)bh * (NTOK * HD);

    int n0 = wm + gid, n1 = wm + gid + 8;

    uint32_t sqB = (uint32_t)__cvta_generic_to_shared(sq);
    uint32_t skB = (uint32_t)__cvta_generic_to_shared(sk);
    uint32_t svB = (uint32_t)__cvta_generic_to_shared(sv);

    int aRow = lane & 15;
    int aCol = (lane >> 4) * 8;
    int bRow = ((lane >> 4) << 3) + (lane & 7);
    int bCol = ((lane >> 3) & 1) * 8;
    int trRow = ((lane >> 3) & 1) * 8 + (lane & 7);
    int trCol = (lane >> 4) * 8;

#pragma unroll
    for (int i = 0; i < 2; i++) {
        int v = tid + i * 128;
        int row = v >> 2, c8 = (v & 3) * 8;
        *(uint4*)&sq[row * 40 + c8] = *(const uint4*)(g_qh + base + row * HD + c8);
        *(uint4*)&sk[row * 40 + c8] = *(const uint4*)(g_kh + base + row * HD + c8);
        *(uint4*)&sv[row * 40 + c8] = *(const uint4*)(g_vh + base + row * HD + c8);
    }
    for (int i = tid; i < 225; i += 128) srel[i] = rel_table[i * NHEAD + head];
    __syncthreads();   // the only block-wide barrier

    // ---- S = q @ k^T ----
    float sacc[8][4];
#pragma unroll
    for (int nt = 0; nt < 8; nt++)
#pragma unroll
        for (int e = 0; e < 4; e++) sacc[nt][e] = 0.0f;

#pragma unroll
    for (int ksi = 0; ksi < 2; ksi++) {
        uint32_t qf[4], bf[8][2];
        ldsm4(qf[0], qf[1], qf[2], qf[3],
              sqB + ((wm + aRow) * 40 + ksi*16 + aCol) * 2);
#pragma unroll
        for (int p = 0; p < 4; p++)
            ldsm4(bf[2*p][0], bf[2*p][1], bf[2*p+1][0], bf[2*p+1][1],
                  skB + ((p*16 + bRow) * 40 + ksi*16 + bCol) * 2);
#pragma unroll
        for (int nt = 0; nt < 8; nt++) mma_f16(sacc[nt], qf, bf[nt]);
    }

    // biases
    float ego_b = ego_table[g_egoidx[b] * NHEAD + head];
    int ny0 = n0 >> 3, nx0 = n0 & 7, ny1 = n1 >> 3, nx1 = n1 & 7;
#pragma unroll
    for (int nt = 0; nt < 8; nt++) {
#pragma unroll
        for (int e = 0; e < 4; e++) {
            int mm = nt * 8 + 2 * tig + (e & 1);
            int my = mm >> 3, mx = mm & 7;
            int ny = (e < 2) ? ny0 : ny1, nx = (e < 2) ? nx0 : nx1;
            sacc[nt][e] += srel[(ny - my + 7) * 15 + (nx - mx + 7)] + ego_b;
        }
    }

    // mixing weights
    float w0 = wvec[0], w1 = wvec[1];
    float mw = fmaxf(w0, w1);
    float e0w = __expf(w0 - mw), e1w = __expf(w1 - mw);
    float inv_w = 1.0f / (e0w + e1w);
    float ws0 = e0w * inv_w, ws1 = e1w * inv_w;

    // ---- softmax, no max-shift, single exp (packed fp16) ----
    float sum0 = 0.0f, sum1 = 0.0f;
    uint32_t ph0[8], ph1[8];
#pragma unroll
    for (int nt = 0; nt < 8; nt++) {
        float e0 = __expf(sacc[nt][0]);
        float e1 = __expf(sacc[nt][1]);
        float e2 = __expf(sacc[nt][2]);
        float e3 = __expf(sacc[nt][3]);
        sum0 += e0 + e1;
        sum1 += e2 + e3;
        __half2 h0 = __floats2half2_rn(e0, e1);
        __half2 h1 = __floats2half2_rn(e2, e3);
        ph0[nt] = *(uint32_t*)&h0;
        ph1[nt] = *(uint32_t*)&h1;
    }
    sum0 += __shfl_xor_sync(0xffffffffu, sum0, 1);
    sum0 += __shfl_xor_sync(0xffffffffu, sum0, 2);
    sum1 += __shfl_xor_sync(0xffffffffu, sum1, 1);
    sum1 += __shfl_xor_sync(0xffffffffu, sum1, 2);
    float i0 = ws0 / sum0, i1 = ws0 / sum1;

    // ---- build P directly as mma A-fragments (no smem) ----
    // C-frag (row gid, cols nt*8+2tig+e | rows gid+8) == A-frag rows/k layout:
    //   pfl[nt] = P(row n0, k = nt*8 + 2tig, +1), pfh[nt] = P(row n1, same k)
    uint32_t pfl[8], pfh[8];
#pragma unroll
    for (int nt = 0; nt < 8; nt++) {
        float2 e01 = __half22float2(*(__half2*)&ph0[nt]);
        float2 e23 = __half22float2(*(__half2*)&ph1[nt]);
        float r0a = fmaxf(sacc[nt][0], 0.0f), r0b = fmaxf(sacc[nt][1], 0.0f);
        float r1a = fmaxf(sacc[nt][2], 0.0f), r1b = fmaxf(sacc[nt][3], 0.0f);
        __half2 P0 = __floats2half2_rn(i0 * e01.x + ws1 * r0a * r0a,
                                       i0 * e01.y + ws1 * r0b * r0b);
        __half2 P1 = __floats2half2_rn(i1 * e23.x + ws1 * r1a * r1a,
                                       i1 * e23.y + ws1 * r1b * r1b);
        pfl[nt] = *(uint32_t*)&P0;
        pfh[nt] = *(uint32_t*)&P1;
    }

    // ---- O = P @ V : A-frags from registers, B-frags via trans-ldmatrix ----
    float oacc[4][4];
#pragma unroll
    for (int nt = 0; nt < 4; nt++)
#pragma unroll
        for (int e = 0; e < 4; e++) oacc[nt][e] = 0.0f;

#pragma unroll
    for (int ksi = 0; ksi < 4; ksi++) {
        uint32_t pf[4], vf[4][2];
        pf[0] = pfl[2*ksi];       // rows gid,   k = ksi*16 + 0..7
        pf[1] = pfh[2*ksi];       // rows gid+8, k low
        pf[2] = pfl[2*ksi + 1];   // rows gid,   k = ksi*16 + 8..15
        pf[3] = pfh[2*ksi + 1];   // rows gid+8, k high
#pragma unroll
        for (int pp = 0; pp < 2; pp++)
            ldsm4t(vf[2*pp][0], vf[2*pp][1], vf[2*pp+1][0], vf[2*pp+1][1],
                   svB + ((ksi*16 + trRow) * 40 + pp*16 + trCol) * 2);
#pragma unroll
        for (int nt = 0; nt < 4; nt++) mma_f16(oacc[nt], pf, vf[nt]);
    }

    __half* aop = g_aoh + (size_t)(b * NTOK) * CH + head * HD;
#pragma unroll
    for (int nt = 0; nt < 4; nt++) {
        int d0 = nt * 8 + 2 * tig;
        __half2 s0 = __floats2half2_rn(oacc[nt][0], oacc[nt][1]);
        __half2 s1 = __floats2half2_rn(oacc[nt][2], oacc[nt][3]);
        *(__half2*)(aop + (size_t)n0 * CH + d0) = s0;
        *(__half2*)(aop + (size_t)n1 * CH + d0) = s1;
    }
}

// ---------------- launch ----------------
extern "C" void kernel_launch(void* const* d_in, const int* in_sizes, int n_in,
                              void* d_out, int out_size) {
    const float* x    = (const float*)d_in[0];
    const float* aff  = (const float*)d_in[1];
    const float* Wq   = (const float*)d_in[2];
    const float* bq   = (const float*)d_in[3];
    const float* Wkv  = (const float*)d_in[4];
    const float* bkv  = (const float*)d_in[5];
    const float* Wp   = (const float*)d_in[6];
    const float* bp   = (const float*)d_in[7];
    const float* rel  = (const float*)d_in[8];
    const float* ego  = (const float*)d_in[9];
    const float* w    = (const float*)d_in[10];
    float* out = (float*)d_out;

    const int GEMM_SMEM = (33792 + 2 * 9216) * 2;   // 104448 B -> 2 CTAs/SM
    static int attr_set = 0;
    if (!attr_set) {
        cudaFuncSetAttribute(gemm_f16, cudaFuncAttributeMaxDynamicSharedMemorySize, GEMM_SMEM);
        attr_set = 1;
    }

    prep_kernel<<<16384 + 768 + 1, 256>>>(x, Wq, bq, Wkv, bkv, Wp, aff);
    gemm_f16<<<dim3(6, 1024), 256, GEMM_SMEM>>>(nullptr, 0, nullptr);
    attn_kernel<<<BWIN * NHEAD, 128>>>(rel, ego, w);
    gemm_f16<<<dim3(2, 1024), 256, GEMM_SMEM>>>(bp, 1, out);
}